// round 14
// baseline (speedup 1.0000x reference)
#include <cuda_runtime.h>
#include <cuda_fp16.h>
#include <cstdint>
#include <math.h>

#define SS 2048
#define DM 1024
#define HH 16
#define DHD 64
#define BB 2
#define MROWS (BB*SS)   // 4096
#define LN_EPS 1e-3f

// ---------------- scratch buffers (no allocation allowed) ----------------
__device__ float g_buf0[MROWS*DM];
__device__ float g_buf1[MROWS*DM];
__device__ __half g_a[MROWS*DM];
__device__ __half g_b[MROWS*DM];
__device__ __half g_q[MROWS*DM];
__device__ __half g_k[MROWS*DM];
__device__ __half g_v[MROWS*DM];
__device__ __half g_wt[6*DM*DM];   // transposed fp16 weights, [N,K] stacked

// ========================= PTX helpers (portable) =========================
__device__ __forceinline__ uint32_t smem_u32(const void* p) {
    uint32_t a;
    asm("{ .reg .u64 t; cvta.to.shared.u64 t, %1; cvt.u32.u64 %0, t; }"
        : "=r"(a) : "l"(p));
    return a;
}
#define CP16(dst, src) \
    asm volatile("cp.async.cg.shared.global [%0], [%1], 16;" \
                 :: "r"(dst), "l"(src) : "memory")
#define CP_COMMIT()  asm volatile("cp.async.commit_group;" ::: "memory")
#define CP_WAIT2()   asm volatile("cp.async.wait_group 2;" ::: "memory")
#define CP_WAIT1()   asm volatile("cp.async.wait_group 1;" ::: "memory")
#define CP_WAIT0()   asm volatile("cp.async.wait_group 0;" ::: "memory")

#define LDSM4(r, addr) \
    asm volatile("ldmatrix.sync.aligned.m8n8.x4.shared.b16 {%0,%1,%2,%3}, [%4];" \
        : "=r"((r)[0]), "=r"((r)[1]), "=r"((r)[2]), "=r"((r)[3]) : "r"(addr))
#define LDSM4T(r, addr) \
    asm volatile("ldmatrix.sync.aligned.m8n8.x4.trans.shared.b16 {%0,%1,%2,%3}, [%4];" \
        : "=r"((r)[0]), "=r"((r)[1]), "=r"((r)[2]), "=r"((r)[3]) : "r"(addr))
#define MMA16816(d, a, b) \
    asm volatile("mma.sync.aligned.m16n8k16.row.col.f32.f16.f16.f32 " \
        "{%0,%1,%2,%3}, {%4,%5,%6,%7}, {%8,%9}, {%0,%1,%2,%3};" \
        : "+f"((d)[0]), "+f"((d)[1]), "+f"((d)[2]), "+f"((d)[3]) \
        : "r"((a)[0]), "r"((a)[1]), "r"((a)[2]), "r"((a)[3]), \
          "r"((b)[0]), "r"((b)[1]))

__device__ __forceinline__ uint32_t packh(float lo, float hi) {
    uint32_t r;
    asm("cvt.rn.f16x2.f32 %0, %1, %2;" : "=r"(r) : "f"(hi), "f"(lo));
    return r;
}

// ==================== fp16 GEMM via mma.sync (HMMA) =======================
// Round-10 proven mainloop body, 2-stage smem (96 KB) with 2 CTAs/SM.
// Safe ordering: WAIT0 + syncthreads precede the next stage's issue, so the
// buffer being overwritten was fully consumed one sync ago.
#define NCH 16              // 1024 / 64
#define STG48 49152         // A 16 KB + B 32 KB
#define SMEM_GEMM (2*STG48)

__device__ __forceinline__ void gemm_issue_stage(
    uint32_t s, int tid, int m0, int n0, int kc,
    const __half* __restrict__ A, const __half* __restrict__ B)
{
    const int g = tid & 7;
#pragma unroll
    for (int i = 0; i < 4; i++) {
        int row = (tid + i * 256) >> 3;
        uint32_t o = row * 128 + g * 16; o ^= (o >> 3) & 0x70;
        CP16(s + o, A + (size_t)(m0 + row) * DM + kc + g * 8);
    }
#pragma unroll
    for (int i = 0; i < 8; i++) {
        int row = (tid + i * 256) >> 3;
        uint32_t o = row * 128 + g * 16; o ^= (o >> 3) & 0x70;
        CP16(s + 16384 + o, B + (size_t)(n0 + row) * DM + kc + g * 8);
    }
}

__global__ __launch_bounds__(256, 2) void gemm_mma_kernel(
    const __half* __restrict__ A, const __half* __restrict__ B,
    float* __restrict__ Cf, __half* __restrict__ Ch0,
    __half* __restrict__ Ch1, __half* __restrict__ Ch2,
    int do_relu, float scale)
{
    extern __shared__ char smem[];
    const uint32_t sb = smem_u32(smem);
    const int tid = threadIdx.x;
    const int lane = tid & 31;
    const int wid = tid >> 5;
    const int wm = wid & 1;
    const int wn = wid >> 1;
    const int m0 = blockIdx.y * 128;
    const int n0 = blockIdx.x * 256;

    float acc[4][8][4];
#pragma unroll
    for (int mt = 0; mt < 4; mt++)
#pragma unroll
        for (int nt = 0; nt < 8; nt++)
#pragma unroll
            for (int r = 0; r < 4; r++) acc[mt][nt][r] = 0.f;

    const int a_row = lane & 15;
    const int a_kb  = (lane >> 4) << 4;
    const int b_row = ((lane >> 4) << 3) + (lane & 7);
    const int b_kb  = ((lane >> 3) & 1) << 4;

    gemm_issue_stage(sb, tid, m0, n0, 0, A, B);
    CP_COMMIT();

    for (int c = 0; c < NCH; c++) {
        CP_WAIT0();
        __syncthreads();
        if (c + 1 < NCH) {
            gemm_issue_stage(sb + ((c + 1) & 1) * STG48, tid, m0, n0,
                             (c + 1) * 64, A, B);
            CP_COMMIT();
        }

        const uint32_t sA = sb + (c & 1) * STG48;
        const uint32_t sB = sA + 16384;

#pragma unroll
        for (int kk = 0; kk < 4; kk++) {
            const int kbyte = kk * 32;
            uint32_t af[4][4], bfr[8][2];

#pragma unroll
            for (int mt = 0; mt < 4; mt++) {
                uint32_t o = (uint32_t)(wm*64 + mt*16 + a_row) * 128 + kbyte + a_kb;
                o ^= (o >> 3) & 0x70;
                LDSM4(af[mt], sA + o);
            }
#pragma unroll
            for (int p = 0; p < 4; p++) {
                uint32_t rr[4];
                uint32_t o = (uint32_t)(wn*64 + p*16 + b_row) * 128 + kbyte + b_kb;
                o ^= (o >> 3) & 0x70;
                LDSM4(rr, sB + o);
                bfr[p*2][0]   = rr[0]; bfr[p*2][1]   = rr[1];
                bfr[p*2+1][0] = rr[2]; bfr[p*2+1][1] = rr[3];
            }
#pragma unroll
            for (int mt = 0; mt < 4; mt++)
#pragma unroll
                for (int nt = 0; nt < 8; nt++)
                    MMA16816(acc[mt][nt], af[mt], bfr[nt]);
        }
    }

    const int which = n0 >> 10;
    __half* Ch = (which == 0) ? Ch0 : ((which == 1) ? Ch1 : Ch2);
    const int ncol = n0 & 1023;
    const float sc = (which == 0) ? scale : 1.f;

#pragma unroll
    for (int mt = 0; mt < 4; mt++) {
        int r0 = m0 + wm*64 + mt*16 + (lane >> 2);
#pragma unroll
        for (int nt = 0; nt < 8; nt++) {
            int cc = ncol + wn*64 + nt*8 + (lane & 3)*2;
            float v[4];
#pragma unroll
            for (int r = 0; r < 4; r++) {
                v[r] = acc[mt][nt][r] * sc;
                if (do_relu) v[r] = fmaxf(v[r], 0.f);
            }
            if (Cf) {
                *(float2*)(Cf + (size_t)r0 * DM + cc)       = make_float2(v[0], v[1]);
                *(float2*)(Cf + (size_t)(r0 + 8) * DM + cc) = make_float2(v[2], v[3]);
            }
            if (Ch) {
                *(uint32_t*)(Ch + (size_t)r0 * DM + cc)     = packh(v[0], v[1]);
                *(uint32_t*)(Ch + (size_t)(r0+8) * DM + cc) = packh(v[2], v[3]);
            }
        }
    }
}

// ======================= fp32 -> fp16 (elementwise) =======================
__global__ __launch_bounds__(256) void cvt_kernel(
    const float4* __restrict__ X, uint32_t* __restrict__ H)
{
    int i = blockIdx.x * 256 + threadIdx.x;
    float4 v = X[i];
    H[i*2+0] = packh(v.x, v.y);
    H[i*2+1] = packh(v.z, v.w);
}

// ==== transpose + cvt, vectorized stores; all 6 weights in one launch =====
struct W6 { const float* p[6]; };

__global__ __launch_bounds__(256) void transpose_cvt_all_kernel(
    W6 ws, __half* __restrict__ T)
{
    __shared__ float t[64][33];
    const int wz = blockIdx.z;
    const float* W = ws.p[wz];
    __half* th = T + (size_t)wz * DM * DM;
    const int n0 = blockIdx.x * 32, k0 = blockIdx.y * 64;
    const int tx = threadIdx.x, ty = threadIdx.y;   // 32 x 8
#pragma unroll
    for (int r = 0; r < 8; r++)
        t[ty + r*8][tx] = W[(size_t)(k0 + ty + r*8) * DM + n0 + tx];
    __syncthreads();
    const int tid = ty * 32 + tx;
#pragma unroll
    for (int w = 0; w < 4; w++) {
        int idx = tid + w * 256;
        int nl = idx >> 5;
        int u  = idx & 31;
        uint32_t pk = packh(t[2*u][nl], t[2*u+1][nl]);
        *(uint32_t*)(th + (size_t)(n0 + nl) * DM + k0 + 2*u) = pk;
    }
}

// ================ tensor-core flash attention, fp16 =======================
// (round-13 proven, unchanged) exp2-domain softmax, Q frags hoisted, paired
// LDSM4/LDSM4T, K/V fragment double-buffering, V j=0 prefetch, 3-stage
// cp.async KV pipeline with one __syncthreads per iteration.
#define AT_Q 0
#define AT_STG 16384
#define AT_STGSZ 16384      // K 8KB + V 8KB
#define SMEM_ATTN (16384 + 3*16384)   // 64 KB
#define NKT (SS/64)

__device__ __forceinline__ void attn_issue_kv(
    uint32_t s, int tid, size_t base, int kt,
    const __half* __restrict__ K, const __half* __restrict__ V)
{
#pragma unroll
    for (int i = 0; i < 2; i++) {
        int idx = tid + i * 256;
        int row = idx >> 3, c16 = idx & 7;
        uint32_t off = row * 128 + c16 * 16;
        off ^= (off >> 3) & 0x70;
        size_t g = base + (size_t)(kt * 64 + row) * DM + c16 * 8;
        CP16(s + off,        K + g);
        CP16(s + 8192 + off, V + g);
    }
}

__global__ __launch_bounds__(256, 2) void attn_mma_kernel(
    const __half* __restrict__ Q, const __half* __restrict__ K,
    const __half* __restrict__ V, __half* __restrict__ O)
{
    extern __shared__ char smem[];
    const uint32_t sb = smem_u32(smem);
    const int tid = threadIdx.x, lane = tid & 31, w = tid >> 5;
    const int q0 = blockIdx.x * 128;
    const int h = blockIdx.y, b = blockIdx.z;
    const size_t base = (size_t)b * SS * DM + h * DHD;

#pragma unroll
    for (int i = 0; i < 4; i++) {
        int idx = tid + i * 256;
        int row = idx >> 3, c16 = idx & 7;
        uint32_t off = row * 128 + c16 * 16;
        off ^= (off >> 3) & 0x70;
        CP16(sb + AT_Q + off, Q + base + (size_t)(q0 + row) * DM + c16 * 8);
    }
    CP_COMMIT();
    attn_issue_kv(sb + AT_STG + 0 * AT_STGSZ, tid, base, 0, K, V);
    CP_COMMIT();
    attn_issue_kv(sb + AT_STG + 1 * AT_STGSZ, tid, base, 1, K, V);
    CP_COMMIT();

    const int arow = w * 16 + (lane & 15);
    const int akb  = (lane >> 4) << 4;
    const int kp_row = ((lane >> 4) << 3) + (lane & 7);
    const int kp_kb  = ((lane >> 3) & 1) << 4;
    const int vp_row = lane & 15;
    const int vp_nb  = (lane >> 4) << 4;

    CP_WAIT2();
    __syncthreads();
    uint32_t aqr[4][4];
#pragma unroll
    for (int ks = 0; ks < 4; ks++) {
        uint32_t o = (uint32_t)arow * 128 + ks * 32 + akb;
        o ^= (o >> 3) & 0x70;
        LDSM4(aqr[ks], sb + AT_Q + o);
    }

    float acco[8][4];
#pragma unroll
    for (int nt = 0; nt < 8; nt++)
#pragma unroll
        for (int r = 0; r < 4; r++) acco[nt][r] = 0.f;
    float runm0 = -1e30f, runm1 = -1e30f, runs0 = 0.f, runs1 = 0.f;

    uint32_t kf[2][4][4];
    uint32_t vf[2][4][4];

    for (int kt = 0; kt < NKT; kt++) {
        if (kt + 1 < NKT) CP_WAIT1(); else CP_WAIT0();
        __syncthreads();
        if (kt + 2 < NKT) {
            attn_issue_kv(sb + AT_STG + ((kt + 2) % 3) * AT_STGSZ, tid, base,
                          kt + 2, K, V);
            CP_COMMIT();
        }

        const uint32_t sK = sb + AT_STG + (kt % 3) * AT_STGSZ;
        const uint32_t sV = sK + 8192;

        auto ldk = [&](int bsel, int ks) {
#pragma unroll
            for (int p = 0; p < 4; p++) {
                uint32_t bo = (uint32_t)(p * 16 + kp_row) * 128 + ks * 32 + kp_kb;
                bo ^= (bo >> 3) & 0x70;
                LDSM4(kf[bsel][p], sK + bo);
            }
        };
        auto ldv = [&](int bsel, int j) {
#pragma unroll
            for (int np = 0; np < 4; np++) {
                uint32_t vo = (uint32_t)(j * 16 + vp_row) * 128 + np * 32 + vp_nb;
                vo ^= (vo >> 3) & 0x70;
                LDSM4T(vf[bsel][np], sV + vo);
            }
        };

        float accs[8][4];
#pragma unroll
        for (int nt = 0; nt < 8; nt++)
#pragma unroll
            for (int r = 0; r < 4; r++) accs[nt][r] = 0.f;

        ldk(0, 0);
#pragma unroll
        for (int ks = 0; ks < 4; ks++) {
            if (ks < 3) ldk((ks + 1) & 1, ks + 1);
            const int cur = ks & 1;
#pragma unroll
            for (int p = 0; p < 4; p++) {
                MMA16816(accs[p*2],   aqr[ks], (kf[cur][p]));
                MMA16816(accs[p*2+1], aqr[ks], (kf[cur][p] + 2));
            }
        }

        ldv(0, 0);   // overlaps softmax below

        float mx0 = -1e30f, mx1 = -1e30f;
#pragma unroll
        for (int nt = 0; nt < 8; nt++) {
            mx0 = fmaxf(mx0, fmaxf(accs[nt][0], accs[nt][1]));
            mx1 = fmaxf(mx1, fmaxf(accs[nt][2], accs[nt][3]));
        }
        mx0 = fmaxf(mx0, __shfl_xor_sync(0xffffffffu, mx0, 1));
        mx0 = fmaxf(mx0, __shfl_xor_sync(0xffffffffu, mx0, 2));
        mx1 = fmaxf(mx1, __shfl_xor_sync(0xffffffffu, mx1, 1));
        mx1 = fmaxf(mx1, __shfl_xor_sync(0xffffffffu, mx1, 2));

        if (mx0 > runm0 || mx1 > runm1) {
            float nm0 = fmaxf(runm0, mx0), nm1 = fmaxf(runm1, mx1);
            float c0 = exp2f(runm0 - nm0), c1 = exp2f(runm1 - nm1);
            runm0 = nm0; runm1 = nm1;
            runs0 *= c0; runs1 *= c1;
#pragma unroll
            for (int nt = 0; nt < 8; nt++) {
                acco[nt][0] *= c0; acco[nt][1] *= c0;
                acco[nt][2] *= c1; acco[nt][3] *= c1;
            }
        }

        float s0 = 0.f, s1 = 0.f;
#pragma unroll
        for (int nt = 0; nt < 8; nt++) {
            accs[nt][0] = exp2f(accs[nt][0] - runm0); s0 += accs[nt][0];
            accs[nt][1] = exp2f(accs[nt][1] - runm0); s0 += accs[nt][1];
            accs[nt][2] = exp2f(accs[nt][2] - runm1); s1 += accs[nt][2];
            accs[nt][3] = exp2f(accs[nt][3] - runm1); s1 += accs[nt][3];
        }
        s0 += __shfl_xor_sync(0xffffffffu, s0, 1);
        s0 += __shfl_xor_sync(0xffffffffu, s0, 2);
        s1 += __shfl_xor_sync(0xffffffffu, s1, 1);
        s1 += __shfl_xor_sync(0xffffffffu, s1, 2);
        runs0 += s0;
        runs1 += s1;

#pragma unroll
        for (int j = 0; j < 4; j++) {
            if (j < 3) ldv((j + 1) & 1, j + 1);
            const int cur = j & 1;
            float* pa = accs[2*j];
            float* pb = accs[2*j + 1];
            uint32_t ap[4];
            ap[0] = packh(pa[0], pa[1]);
            ap[1] = packh(pa[2], pa[3]);
            ap[2] = packh(pb[0], pb[1]);
            ap[3] = packh(pb[2], pb[3]);
#pragma unroll
            for (int np = 0; np < 4; np++) {
                MMA16816(acco[np*2],   ap, (vf[cur][np]));
                MMA16816(acco[np*2+1], ap, (vf[cur][np] + 2));
            }
        }
    }

    const float i0 = 1.f / runs0, i1 = 1.f / runs1;
    const size_t r0 = (size_t)(b * SS + q0 + w * 16 + (lane >> 2));
#pragma unroll
    for (int nt = 0; nt < 8; nt++) {
        int cc = h * DHD + nt * 8 + (lane & 3) * 2;
        *(uint32_t*)(O + r0 * DM + cc)     = packh(acco[nt][0]*i0, acco[nt][1]*i0);
        *(uint32_t*)(O + (r0+8) * DM + cc) = packh(acco[nt][2]*i1, acco[nt][3]*i1);
    }
}

// ======================= residual-add + LayerNorm =========================
__device__ __forceinline__ float block_sum256(float v, float* red) {
#pragma unroll
    for (int o = 16; o; o >>= 1) v += __shfl_xor_sync(0xffffffffu, v, o);
    int lane = threadIdx.x & 31, wid = threadIdx.x >> 5;
    if (lane == 0) red[wid] = v;
    __syncthreads();
    if (threadIdx.x < 32) {
        float t = (threadIdx.x < 8) ? red[threadIdx.x] : 0.f;
#pragma unroll
        for (int o = 4; o; o >>= 1) t += __shfl_xor_sync(0xffffffffu, t, o);
        if (threadIdx.x == 0) red[0] = t;
    }
    __syncthreads();
    float r = red[0];
    __syncthreads();
    return r;
}

__global__ __launch_bounds__(256) void ln_kernel(
    const float* __restrict__ x, const float* __restrict__ res,
    const float* __restrict__ gamma, const float* __restrict__ beta,
    float* __restrict__ out, __half* __restrict__ oh)
{
    __shared__ float red[8];
    const int row = blockIdx.x;
    const int tid = threadIdx.x;

    float4 v = ((const float4*)(x + (size_t)row * DM))[tid];
    float4 r = ((const float4*)(res + (size_t)row * DM))[tid];
    v.x += r.x; v.y += r.y; v.z += r.z; v.w += r.w;

    float s = v.x + v.y + v.z + v.w;
    float tot = block_sum256(s, red);
    float mean = tot * (1.f / DM);

    float dx = v.x - mean, dy = v.y - mean, dz = v.z - mean, dw = v.w - mean;
    float sq = dx*dx + dy*dy + dz*dz + dw*dw;
    float totsq = block_sum256(sq, red);
    float rstd = rsqrtf(totsq * (1.f / DM) + LN_EPS);

    float4 g = ((const float4*)gamma)[tid];
    float4 bb = ((const float4*)beta)[tid];
    float4 o;
    o.x = dx * rstd * g.x + bb.x;
    o.y = dy * rstd * g.y + bb.y;
    o.z = dz * rstd * g.z + bb.z;
    o.w = dw * rstd * g.w + bb.w;
    if (out) ((float4*)(out + (size_t)row * DM))[tid] = o;
    if (oh) {
        uint32_t* hp = (uint32_t*)(oh + (size_t)row * DM) + tid*2;
        hp[0] = packh(o.x, o.y);
        hp[1] = packh(o.z, o.w);
    }
}

// ================================ driver ==================================
extern "C" void kernel_launch(void* const* d_in, const int* in_sizes, int n_in,
                              void* d_out, int out_size)
{
    const float* query = (const float*)d_in[0];
    const float* gamma = (const float*)d_in[7];
    const float* beta  = (const float*)d_in[8];

    float *b0, *b1;
    __half *ah, *bh, *qh, *kh, *vh, *wt;
    cudaGetSymbolAddress((void**)&b0, g_buf0);
    cudaGetSymbolAddress((void**)&b1, g_buf1);
    cudaGetSymbolAddress((void**)&ah, g_a);
    cudaGetSymbolAddress((void**)&bh, g_b);
    cudaGetSymbolAddress((void**)&qh, g_q);
    cudaGetSymbolAddress((void**)&kh, g_k);
    cudaGetSymbolAddress((void**)&vh, g_v);
    cudaGetSymbolAddress((void**)&wt, g_wt);

    cudaFuncSetAttribute(gemm_mma_kernel,
                         cudaFuncAttributeMaxDynamicSharedMemorySize, SMEM_GEMM);
    cudaFuncSetAttribute(attn_mma_kernel,
                         cudaFuncAttributeMaxDynamicSharedMemorySize, SMEM_ATTN);

    const dim3 ggrid(DM / 256, MROWS / 128);          // (4, 32)
    const dim3 ggrid_qkv(3 * DM / 256, MROWS / 128);  // (12, 32)
    const int cvt_blocks = (MROWS * DM / 4) / 256;
    const float QSCALE = 0.125f * 1.44269504088896f;  // fold log2(e) for exp2

    // weight transform: transpose + cvt, all 6 in one launch
    W6 ws;
    for (int i = 0; i < 6; i++) ws.p[i] = (const float*)d_in[1 + i];
    transpose_cvt_all_kernel<<<dim3(DM/32, DM/64, 6), dim3(32, 8)>>>(ws, wt);

    // query -> fp16
    cvt_kernel<<<cvt_blocks, 256>>>((const float4*)query, (uint32_t*)ah);

    // merged QKV projection (N = 3072; Q pre-scaled into exp2 domain)
    gemm_mma_kernel<<<ggrid_qkv, 256, SMEM_GEMM>>>(
        ah, wt, nullptr, qh, kh, vh, 0, QSCALE);

    // attention -> ctx fp16 in ah
    attn_mma_kernel<<<dim3(SS/128, HH, BB), 256, SMEM_ATTN>>>(qh, kh, vh, ah);

    // ctx @ W1 -> fp32 b0 ; LN(b0 + query) -> fp32 b1 + fp16 ah
    gemm_mma_kernel<<<ggrid, 256, SMEM_GEMM>>>(
        ah, wt + 3*(size_t)DM*DM, b0, nullptr, nullptr, nullptr, 0, 1.f);
    ln_kernel<<<MROWS, 256>>>(b0, query, gamma, beta, b1, ah);

    // relu(residual @ W2) -> fp16 bh ; bh @ W3 -> fp32 b0 ; LN -> out
    gemm_mma_kernel<<<ggrid, 256, SMEM_GEMM>>>(
        ah, wt + 4*(size_t)DM*DM, nullptr, bh, bh, bh, 1, 1.f);
    gemm_mma_kernel<<<ggrid, 256, SMEM_GEMM>>>(
        bh, wt + 5*(size_t)DM*DM, b0, nullptr, nullptr, nullptr, 0, 1.f);
    ln_kernel<<<MROWS, 256>>>(b0, b1, gamma, beta, (float*)d_out, nullptr);
}

// round 15
// speedup vs baseline: 2.0769x; 2.0769x over previous
#include <cuda_runtime.h>
#include <cuda_fp16.h>
#include <cstdint>
#include <math.h>

#define SS 2048
#define DM 1024
#define HH 16
#define DHD 64
#define BB 2
#define MROWS (BB*SS)   // 4096
#define LN_EPS 1e-3f

// ---------------- scratch buffers (no allocation allowed) ----------------
__device__ float g_buf0[MROWS*DM];
__device__ float g_buf1[MROWS*DM];
__device__ __half g_a[MROWS*DM];
__device__ __half g_b[MROWS*DM];
__device__ __half g_q[MROWS*DM];
__device__ __half g_k[MROWS*DM];
__device__ __half g_v[MROWS*DM];
__device__ __half g_wt[6*DM*DM];   // transposed fp16 weights, [N,K] stacked

// ========================= PTX helpers (portable) =========================
__device__ __forceinline__ uint32_t smem_u32(const void* p) {
    uint32_t a;
    asm("{ .reg .u64 t; cvta.to.shared.u64 t, %1; cvt.u32.u64 %0, t; }"
        : "=r"(a) : "l"(p));
    return a;
}
#define CP16(dst, src) \
    asm volatile("cp.async.cg.shared.global [%0], [%1], 16;" \
                 :: "r"(dst), "l"(src) : "memory")
#define CP_COMMIT()  asm volatile("cp.async.commit_group;" ::: "memory")
#define CP_WAIT2()   asm volatile("cp.async.wait_group 2;" ::: "memory")
#define CP_WAIT1()   asm volatile("cp.async.wait_group 1;" ::: "memory")
#define CP_WAIT0()   asm volatile("cp.async.wait_group 0;" ::: "memory")

#define LDSM4(r, addr) \
    asm volatile("ldmatrix.sync.aligned.m8n8.x4.shared.b16 {%0,%1,%2,%3}, [%4];" \
        : "=r"((r)[0]), "=r"((r)[1]), "=r"((r)[2]), "=r"((r)[3]) : "r"(addr))
#define LDSM4T(r, addr) \
    asm volatile("ldmatrix.sync.aligned.m8n8.x4.trans.shared.b16 {%0,%1,%2,%3}, [%4];" \
        : "=r"((r)[0]), "=r"((r)[1]), "=r"((r)[2]), "=r"((r)[3]) : "r"(addr))
#define MMA16816(d, a, b) \
    asm volatile("mma.sync.aligned.m16n8k16.row.col.f32.f16.f16.f32 " \
        "{%0,%1,%2,%3}, {%4,%5,%6,%7}, {%8,%9}, {%0,%1,%2,%3};" \
        : "+f"((d)[0]), "+f"((d)[1]), "+f"((d)[2]), "+f"((d)[3]) \
        : "r"((a)[0]), "r"((a)[1]), "r"((a)[2]), "r"((a)[3]), \
          "r"((b)[0]), "r"((b)[1]))

__device__ __forceinline__ uint32_t packh(float lo, float hi) {
    uint32_t r;
    asm("cvt.rn.f16x2.f32 %0, %1, %2;" : "=r"(r) : "f"(hi), "f"(lo));
    return r;
}

// ==================== fp16 GEMM via mma.sync (HMMA) =======================
// ROUND-13 EXACT (measured 27.5 us/GEMM): CTA 128x256, 256 threads
// (8 warps, 2Mx4N), warp tile 64x64, K-chunk 64, 3-stage cp.async,
// 144 KB smem, 1 CTA/SM (needs ~240 regs; minblocks>=2 would spill).
#define NCH 16              // 1024 / 64
#define STG48 49152         // A 16 KB + B 32 KB
#define SMEM_GEMM (3*STG48)

__device__ __forceinline__ void gemm_issue_stage(
    uint32_t s, int tid, int m0, int n0, int kc,
    const __half* __restrict__ A, const __half* __restrict__ B)
{
    const int g = tid & 7;
#pragma unroll
    for (int i = 0; i < 4; i++) {
        int row = (tid + i * 256) >> 3;
        uint32_t o = row * 128 + g * 16; o ^= (o >> 3) & 0x70;
        CP16(s + o, A + (size_t)(m0 + row) * DM + kc + g * 8);
    }
#pragma unroll
    for (int i = 0; i < 8; i++) {
        int row = (tid + i * 256) >> 3;
        uint32_t o = row * 128 + g * 16; o ^= (o >> 3) & 0x70;
        CP16(s + 16384 + o, B + (size_t)(n0 + row) * DM + kc + g * 8);
    }
}

__global__ __launch_bounds__(256, 1) void gemm_mma_kernel(
    const __half* __restrict__ A, const __half* __restrict__ B,
    float* __restrict__ Cf, __half* __restrict__ Ch0,
    __half* __restrict__ Ch1, __half* __restrict__ Ch2,
    int do_relu, float scale)
{
    extern __shared__ char smem[];
    const uint32_t sb = smem_u32(smem);
    const int tid = threadIdx.x;
    const int lane = tid & 31;
    const int wid = tid >> 5;
    const int wm = wid & 1;
    const int wn = wid >> 1;
    const int m0 = blockIdx.y * 128;
    const int n0 = blockIdx.x * 256;

    float acc[4][8][4];
#pragma unroll
    for (int mt = 0; mt < 4; mt++)
#pragma unroll
        for (int nt = 0; nt < 8; nt++)
#pragma unroll
            for (int r = 0; r < 4; r++) acc[mt][nt][r] = 0.f;

    const int a_row = lane & 15;
    const int a_kb  = (lane >> 4) << 4;
    const int b_row = ((lane >> 4) << 3) + (lane & 7);
    const int b_kb  = ((lane >> 3) & 1) << 4;

    gemm_issue_stage(sb, tid, m0, n0, 0, A, B);
    CP_COMMIT();
    gemm_issue_stage(sb + STG48, tid, m0, n0, 64, A, B);
    CP_COMMIT();

    for (int c = 0; c < NCH; c++) {
        if (c + 1 < NCH) CP_WAIT1(); else CP_WAIT0();
        __syncthreads();

        const uint32_t sA = sb + (c % 3) * STG48;
        const uint32_t sB = sA + 16384;

#pragma unroll
        for (int kk = 0; kk < 4; kk++) {
            const int kbyte = kk * 32;
            uint32_t af[4][4], bfr[8][2];

#pragma unroll
            for (int mt = 0; mt < 4; mt++) {
                uint32_t o = (uint32_t)(wm*64 + mt*16 + a_row) * 128 + kbyte + a_kb;
                o ^= (o >> 3) & 0x70;
                LDSM4(af[mt], sA + o);
            }
#pragma unroll
            for (int p = 0; p < 4; p++) {
                uint32_t rr[4];
                uint32_t o = (uint32_t)(wn*64 + p*16 + b_row) * 128 + kbyte + b_kb;
                o ^= (o >> 3) & 0x70;
                LDSM4(rr, sB + o);
                bfr[p*2][0]   = rr[0]; bfr[p*2][1]   = rr[1];
                bfr[p*2+1][0] = rr[2]; bfr[p*2+1][1] = rr[3];
            }
#pragma unroll
            for (int mt = 0; mt < 4; mt++)
#pragma unroll
                for (int nt = 0; nt < 8; nt++)
                    MMA16816(acc[mt][nt], af[mt], bfr[nt]);
        }

        if (c + 2 < NCH) {
            gemm_issue_stage(sb + ((c + 2) % 3) * STG48, tid, m0, n0,
                             (c + 2) * 64, A, B);
            CP_COMMIT();
        }
    }

    const int which = n0 >> 10;
    __half* Ch = (which == 0) ? Ch0 : ((which == 1) ? Ch1 : Ch2);
    const int ncol = n0 & 1023;
    const float sc = (which == 0) ? scale : 1.f;

#pragma unroll
    for (int mt = 0; mt < 4; mt++) {
        int r0 = m0 + wm*64 + mt*16 + (lane >> 2);
#pragma unroll
        for (int nt = 0; nt < 8; nt++) {
            int cc = ncol + wn*64 + nt*8 + (lane & 3)*2;
            float v[4];
#pragma unroll
            for (int r = 0; r < 4; r++) {
                v[r] = acc[mt][nt][r] * sc;
                if (do_relu) v[r] = fmaxf(v[r], 0.f);
            }
            if (Cf) {
                *(float2*)(Cf + (size_t)r0 * DM + cc)       = make_float2(v[0], v[1]);
                *(float2*)(Cf + (size_t)(r0 + 8) * DM + cc) = make_float2(v[2], v[3]);
            }
            if (Ch) {
                *(uint32_t*)(Ch + (size_t)r0 * DM + cc)     = packh(v[0], v[1]);
                *(uint32_t*)(Ch + (size_t)(r0+8) * DM + cc) = packh(v[2], v[3]);
            }
        }
    }
}

// ===== prep: transpose+cvt 6 weights (z=0..5) + query cvt (z=6) ==========
struct PrepArgs {
    const float* w[6];
    const float4* q;
    uint2* qd;
};

__global__ __launch_bounds__(256) void prep_kernel(
    PrepArgs pa, __half* __restrict__ T)
{
    const int wz = blockIdx.z;
    if (wz < 6) {
        __shared__ float t[64][33];
        const float* W = pa.w[wz];
        __half* th = T + (size_t)wz * DM * DM;
        const int n0 = blockIdx.x * 32, k0 = blockIdx.y * 64;
        const int tx = threadIdx.x & 31, ty = threadIdx.x >> 5;   // 32 x 8
#pragma unroll
        for (int r = 0; r < 8; r++)
            t[ty + r*8][tx] = W[(size_t)(k0 + ty + r*8) * DM + n0 + tx];
        __syncthreads();
        const int tid = threadIdx.x;
#pragma unroll
        for (int w = 0; w < 4; w++) {
            int idx = tid + w * 256;
            int nl = idx >> 5;
            int u  = idx & 31;
            uint32_t pk = packh(t[2*u][nl], t[2*u+1][nl]);
            *(uint32_t*)(th + (size_t)(n0 + nl) * DM + k0 + 2*u) = pk;
        }
    } else {
        // query cvt: grid (32,16) blocks x 256 thr, 8 float4 per thread
        const int blk = blockIdx.y * 32 + blockIdx.x;   // 0..511
#pragma unroll
        for (int w = 0; w < 8; w++) {
            int i = (blk * 8 + w) * 256 + threadIdx.x;
            float4 v = pa.q[i];
            uint2 o;
            o.x = packh(v.x, v.y);
            o.y = packh(v.z, v.w);
            pa.qd[i] = o;
        }
    }
}

// ================ tensor-core flash attention, fp16 =======================
// (round-13 proven, unchanged) exp2-domain softmax, Q frags hoisted, paired
// LDSM4/LDSM4T, K/V fragment double-buffering, V j=0 prefetch, 3-stage
// cp.async KV pipeline with one __syncthreads per iteration.
#define AT_Q 0
#define AT_STG 16384
#define AT_STGSZ 16384      // K 8KB + V 8KB
#define SMEM_ATTN (16384 + 3*16384)   // 64 KB
#define NKT (SS/64)

__device__ __forceinline__ void attn_issue_kv(
    uint32_t s, int tid, size_t base, int kt,
    const __half* __restrict__ K, const __half* __restrict__ V)
{
#pragma unroll
    for (int i = 0; i < 2; i++) {
        int idx = tid + i * 256;
        int row = idx >> 3, c16 = idx & 7;
        uint32_t off = row * 128 + c16 * 16;
        off ^= (off >> 3) & 0x70;
        size_t g = base + (size_t)(kt * 64 + row) * DM + c16 * 8;
        CP16(s + off,        K + g);
        CP16(s + 8192 + off, V + g);
    }
}

__global__ __launch_bounds__(256, 2) void attn_mma_kernel(
    const __half* __restrict__ Q, const __half* __restrict__ K,
    const __half* __restrict__ V, __half* __restrict__ O)
{
    extern __shared__ char smem[];
    const uint32_t sb = smem_u32(smem);
    const int tid = threadIdx.x, lane = tid & 31, w = tid >> 5;
    const int q0 = blockIdx.x * 128;
    const int h = blockIdx.y, b = blockIdx.z;
    const size_t base = (size_t)b * SS * DM + h * DHD;

#pragma unroll
    for (int i = 0; i < 4; i++) {
        int idx = tid + i * 256;
        int row = idx >> 3, c16 = idx & 7;
        uint32_t off = row * 128 + c16 * 16;
        off ^= (off >> 3) & 0x70;
        CP16(sb + AT_Q + off, Q + base + (size_t)(q0 + row) * DM + c16 * 8);
    }
    CP_COMMIT();
    attn_issue_kv(sb + AT_STG + 0 * AT_STGSZ, tid, base, 0, K, V);
    CP_COMMIT();
    attn_issue_kv(sb + AT_STG + 1 * AT_STGSZ, tid, base, 1, K, V);
    CP_COMMIT();

    const int arow = w * 16 + (lane & 15);
    const int akb  = (lane >> 4) << 4;
    const int kp_row = ((lane >> 4) << 3) + (lane & 7);
    const int kp_kb  = ((lane >> 3) & 1) << 4;
    const int vp_row = lane & 15;
    const int vp_nb  = (lane >> 4) << 4;

    CP_WAIT2();
    __syncthreads();
    uint32_t aqr[4][4];
#pragma unroll
    for (int ks = 0; ks < 4; ks++) {
        uint32_t o = (uint32_t)arow * 128 + ks * 32 + akb;
        o ^= (o >> 3) & 0x70;
        LDSM4(aqr[ks], sb + AT_Q + o);
    }

    float acco[8][4];
#pragma unroll
    for (int nt = 0; nt < 8; nt++)
#pragma unroll
        for (int r = 0; r < 4; r++) acco[nt][r] = 0.f;
    float runm0 = -1e30f, runm1 = -1e30f, runs0 = 0.f, runs1 = 0.f;

    uint32_t kf[2][4][4];
    uint32_t vf[2][4][4];

    for (int kt = 0; kt < NKT; kt++) {
        if (kt + 1 < NKT) CP_WAIT1(); else CP_WAIT0();
        __syncthreads();
        if (kt + 2 < NKT) {
            attn_issue_kv(sb + AT_STG + ((kt + 2) % 3) * AT_STGSZ, tid, base,
                          kt + 2, K, V);
            CP_COMMIT();
        }

        const uint32_t sK = sb + AT_STG + (kt % 3) * AT_STGSZ;
        const uint32_t sV = sK + 8192;

        auto ldk = [&](int bsel, int ks) {
#pragma unroll
            for (int p = 0; p < 4; p++) {
                uint32_t bo = (uint32_t)(p * 16 + kp_row) * 128 + ks * 32 + kp_kb;
                bo ^= (bo >> 3) & 0x70;
                LDSM4(kf[bsel][p], sK + bo);
            }
        };
        auto ldv = [&](int bsel, int j) {
#pragma unroll
            for (int np = 0; np < 4; np++) {
                uint32_t vo = (uint32_t)(j * 16 + vp_row) * 128 + np * 32 + vp_nb;
                vo ^= (vo >> 3) & 0x70;
                LDSM4T(vf[bsel][np], sV + vo);
            }
        };

        float accs[8][4];
#pragma unroll
        for (int nt = 0; nt < 8; nt++)
#pragma unroll
            for (int r = 0; r < 4; r++) accs[nt][r] = 0.f;

        ldk(0, 0);
#pragma unroll
        for (int ks = 0; ks < 4; ks++) {
            if (ks < 3) ldk((ks + 1) & 1, ks + 1);
            const int cur = ks & 1;
#pragma unroll
            for (int p = 0; p < 4; p++) {
                MMA16816(accs[p*2],   aqr[ks], (kf[cur][p]));
                MMA16816(accs[p*2+1], aqr[ks], (kf[cur][p] + 2));
            }
        }

        ldv(0, 0);   // overlaps softmax below

        float mx0 = -1e30f, mx1 = -1e30f;
#pragma unroll
        for (int nt = 0; nt < 8; nt++) {
            mx0 = fmaxf(mx0, fmaxf(accs[nt][0], accs[nt][1]));
            mx1 = fmaxf(mx1, fmaxf(accs[nt][2], accs[nt][3]));
        }
        mx0 = fmaxf(mx0, __shfl_xor_sync(0xffffffffu, mx0, 1));
        mx0 = fmaxf(mx0, __shfl_xor_sync(0xffffffffu, mx0, 2));
        mx1 = fmaxf(mx1, __shfl_xor_sync(0xffffffffu, mx1, 1));
        mx1 = fmaxf(mx1, __shfl_xor_sync(0xffffffffu, mx1, 2));

        if (mx0 > runm0 || mx1 > runm1) {
            float nm0 = fmaxf(runm0, mx0), nm1 = fmaxf(runm1, mx1);
            float c0 = exp2f(runm0 - nm0), c1 = exp2f(runm1 - nm1);
            runm0 = nm0; runm1 = nm1;
            runs0 *= c0; runs1 *= c1;
#pragma unroll
            for (int nt = 0; nt < 8; nt++) {
                acco[nt][0] *= c0; acco[nt][1] *= c0;
                acco[nt][2] *= c1; acco[nt][3] *= c1;
            }
        }

        float s0 = 0.f, s1 = 0.f;
#pragma unroll
        for (int nt = 0; nt < 8; nt++) {
            accs[nt][0] = exp2f(accs[nt][0] - runm0); s0 += accs[nt][0];
            accs[nt][1] = exp2f(accs[nt][1] - runm0); s0 += accs[nt][1];
            accs[nt][2] = exp2f(accs[nt][2] - runm1); s1 += accs[nt][2];
            accs[nt][3] = exp2f(accs[nt][3] - runm1); s1 += accs[nt][3];
        }
        s0 += __shfl_xor_sync(0xffffffffu, s0, 1);
        s0 += __shfl_xor_sync(0xffffffffu, s0, 2);
        s1 += __shfl_xor_sync(0xffffffffu, s1, 1);
        s1 += __shfl_xor_sync(0xffffffffu, s1, 2);
        runs0 += s0;
        runs1 += s1;

#pragma unroll
        for (int j = 0; j < 4; j++) {
            if (j < 3) ldv((j + 1) & 1, j + 1);
            const int cur = j & 1;
            float* pa = accs[2*j];
            float* pb = accs[2*j + 1];
            uint32_t ap[4];
            ap[0] = packh(pa[0], pa[1]);
            ap[1] = packh(pa[2], pa[3]);
            ap[2] = packh(pb[0], pb[1]);
            ap[3] = packh(pb[2], pb[3]);
#pragma unroll
            for (int np = 0; np < 4; np++) {
                MMA16816(acco[np*2],   ap, (vf[cur][np]));
                MMA16816(acco[np*2+1], ap, (vf[cur][np] + 2));
            }
        }
    }

    const float i0 = 1.f / runs0, i1 = 1.f / runs1;
    const size_t r0 = (size_t)(b * SS + q0 + w * 16 + (lane >> 2));
#pragma unroll
    for (int nt = 0; nt < 8; nt++) {
        int cc = h * DHD + nt * 8 + (lane & 3) * 2;
        *(uint32_t*)(O + r0 * DM + cc)     = packh(acco[nt][0]*i0, acco[nt][1]*i0);
        *(uint32_t*)(O + (r0+8) * DM + cc) = packh(acco[nt][2]*i1, acco[nt][3]*i1);
    }
}

// ======================= residual-add + LayerNorm =========================
__device__ __forceinline__ float block_sum256(float v, float* red) {
#pragma unroll
    for (int o = 16; o; o >>= 1) v += __shfl_xor_sync(0xffffffffu, v, o);
    int lane = threadIdx.x & 31, wid = threadIdx.x >> 5;
    if (lane == 0) red[wid] = v;
    __syncthreads();
    if (threadIdx.x < 32) {
        float t = (threadIdx.x < 8) ? red[threadIdx.x] : 0.f;
#pragma unroll
        for (int o = 4; o; o >>= 1) t += __shfl_xor_sync(0xffffffffu, t, o);
        if (threadIdx.x == 0) red[0] = t;
    }
    __syncthreads();
    float r = red[0];
    __syncthreads();
    return r;
}

__global__ __launch_bounds__(256) void ln_kernel(
    const float* __restrict__ x, const float* __restrict__ res,
    const float* __restrict__ gamma, const float* __restrict__ beta,
    float* __restrict__ out, __half* __restrict__ oh)
{
    __shared__ float red[8];
    const int row = blockIdx.x;
    const int tid = threadIdx.x;

    float4 v = ((const float4*)(x + (size_t)row * DM))[tid];
    float4 r = ((const float4*)(res + (size_t)row * DM))[tid];
    v.x += r.x; v.y += r.y; v.z += r.z; v.w += r.w;

    float s = v.x + v.y + v.z + v.w;
    float tot = block_sum256(s, red);
    float mean = tot * (1.f / DM);

    float dx = v.x - mean, dy = v.y - mean, dz = v.z - mean, dw = v.w - mean;
    float sq = dx*dx + dy*dy + dz*dz + dw*dw;
    float totsq = block_sum256(sq, red);
    float rstd = rsqrtf(totsq * (1.f / DM) + LN_EPS);

    float4 g = ((const float4*)gamma)[tid];
    float4 bb = ((const float4*)beta)[tid];
    float4 o;
    o.x = dx * rstd * g.x + bb.x;
    o.y = dy * rstd * g.y + bb.y;
    o.z = dz * rstd * g.z + bb.z;
    o.w = dw * rstd * g.w + bb.w;
    if (out) ((float4*)(out + (size_t)row * DM))[tid] = o;
    if (oh) {
        uint32_t* hp = (uint32_t*)(oh + (size_t)row * DM) + tid*2;
        hp[0] = packh(o.x, o.y);
        hp[1] = packh(o.z, o.w);
    }
}

// ================================ driver ==================================
extern "C" void kernel_launch(void* const* d_in, const int* in_sizes, int n_in,
                              void* d_out, int out_size)
{
    const float* query = (const float*)d_in[0];
    const float* gamma = (const float*)d_in[7];
    const float* beta  = (const float*)d_in[8];

    float *b0, *b1;
    __half *ah, *bh, *qh, *kh, *vh, *wt;
    cudaGetSymbolAddress((void**)&b0, g_buf0);
    cudaGetSymbolAddress((void**)&b1, g_buf1);
    cudaGetSymbolAddress((void**)&ah, g_a);
    cudaGetSymbolAddress((void**)&bh, g_b);
    cudaGetSymbolAddress((void**)&qh, g_q);
    cudaGetSymbolAddress((void**)&kh, g_k);
    cudaGetSymbolAddress((void**)&vh, g_v);
    cudaGetSymbolAddress((void**)&wt, g_wt);

    cudaFuncSetAttribute(gemm_mma_kernel,
                         cudaFuncAttributeMaxDynamicSharedMemorySize, SMEM_GEMM);
    cudaFuncSetAttribute(attn_mma_kernel,
                         cudaFuncAttributeMaxDynamicSharedMemorySize, SMEM_ATTN);

    const dim3 ggrid(DM / 256, MROWS / 128);          // (4, 32)
    const dim3 ggrid_qkv(3 * DM / 256, MROWS / 128);  // (12, 32)
    const float QSCALE = 0.125f * 1.44269504088896f;  // fold log2(e) for exp2

    // merged prep: 6 weight transpose+cvt slices + query cvt slice
    PrepArgs pa;
    for (int i = 0; i < 6; i++) pa.w[i] = (const float*)d_in[1 + i];
    pa.q  = (const float4*)query;
    pa.qd = (uint2*)ah;
    prep_kernel<<<dim3(DM/32, DM/64, 7), 256>>>(pa, wt);

    // merged QKV projection (N = 3072; Q pre-scaled into exp2 domain)
    gemm_mma_kernel<<<ggrid_qkv, 256, SMEM_GEMM>>>(
        ah, wt, nullptr, qh, kh, vh, 0, QSCALE);

    // attention -> ctx fp16 in ah
    attn_mma_kernel<<<dim3(SS/128, HH, BB), 256, SMEM_ATTN>>>(qh, kh, vh, ah);

    // ctx @ W1 -> fp32 b0 ; LN(b0 + query) -> fp32 b1 + fp16 ah
    gemm_mma_kernel<<<ggrid, 256, SMEM_GEMM>>>(
        ah, wt + 3*(size_t)DM*DM, b0, nullptr, nullptr, nullptr, 0, 1.f);
    ln_kernel<<<MROWS, 256>>>(b0, query, gamma, beta, b1, ah);

    // relu(residual @ W2) -> fp16 bh ; bh @ W3 -> fp32 b0 ; LN -> out
    gemm_mma_kernel<<<ggrid, 256, SMEM_GEMM>>>(
        ah, wt + 4*(size_t)DM*DM, nullptr, bh, bh, bh, 1, 1.f);
    gemm_mma_kernel<<<ggrid, 256, SMEM_GEMM>>>(
        bh, wt + 5*(size_t)DM*DM, b0, nullptr, nullptr, nullptr, 0, 1.f);
    ln_kernel<<<MROWS, 256>>>(b0, b1, gamma, beta, (float*)d_out, nullptr);
}

// round 16
// speedup vs baseline: 2.0795x; 1.0012x over previous
#include <cuda_runtime.h>
#include <cuda_fp16.h>
#include <cstdint>
#include <math.h>

#define SS 2048
#define DM 1024
#define HH 16
#define DHD 64
#define BB 2
#define MROWS (BB*SS)   // 4096
#define LN_EPS 1e-3f

// ---------------- scratch buffers (no allocation allowed) ----------------
__device__ float g_buf0[MROWS*DM];
__device__ float g_buf1[MROWS*DM];
__device__ __half g_a[MROWS*DM];
__device__ __half g_b[MROWS*DM];
__device__ __half g_q[MROWS*DM];
__device__ __half g_k[MROWS*DM];
__device__ __half g_v[MROWS*DM];
__device__ __half g_wt[6*DM*DM];   // transposed fp16 weights, [N,K] stacked

// ========================= PTX helpers (portable) =========================
__device__ __forceinline__ uint32_t smem_u32(const void* p) {
    uint32_t a;
    asm("{ .reg .u64 t; cvta.to.shared.u64 t, %1; cvt.u32.u64 %0, t; }"
        : "=r"(a) : "l"(p));
    return a;
}
#define CP16(dst, src) \
    asm volatile("cp.async.cg.shared.global [%0], [%1], 16;" \
                 :: "r"(dst), "l"(src) : "memory")
#define CP_COMMIT()  asm volatile("cp.async.commit_group;" ::: "memory")
#define CP_WAIT2()   asm volatile("cp.async.wait_group 2;" ::: "memory")
#define CP_WAIT1()   asm volatile("cp.async.wait_group 1;" ::: "memory")
#define CP_WAIT0()   asm volatile("cp.async.wait_group 0;" ::: "memory")

#define LDSM4(r, addr) \
    asm volatile("ldmatrix.sync.aligned.m8n8.x4.shared.b16 {%0,%1,%2,%3}, [%4];" \
        : "=r"((r)[0]), "=r"((r)[1]), "=r"((r)[2]), "=r"((r)[3]) : "r"(addr))
#define LDSM4T(r, addr) \
    asm volatile("ldmatrix.sync.aligned.m8n8.x4.trans.shared.b16 {%0,%1,%2,%3}, [%4];" \
        : "=r"((r)[0]), "=r"((r)[1]), "=r"((r)[2]), "=r"((r)[3]) : "r"(addr))
#define MMA16816(d, a, b) \
    asm volatile("mma.sync.aligned.m16n8k16.row.col.f32.f16.f16.f32 " \
        "{%0,%1,%2,%3}, {%4,%5,%6,%7}, {%8,%9}, {%0,%1,%2,%3};" \
        : "+f"((d)[0]), "+f"((d)[1]), "+f"((d)[2]), "+f"((d)[3]) \
        : "r"((a)[0]), "r"((a)[1]), "r"((a)[2]), "r"((a)[3]), \
          "r"((b)[0]), "r"((b)[1]))

__device__ __forceinline__ uint32_t packh(float lo, float hi) {
    uint32_t r;
    asm("cvt.rn.f16x2.f32 %0, %1, %2;" : "=r"(r) : "f"(hi), "f"(lo));
    return r;
}

// ==================== fp16 GEMM via mma.sync (HMMA) =======================
// ROUND-15 EXACT (measured 28.4 us/GEMM, regs 242).
#define NCH 16              // 1024 / 64
#define STG48 49152         // A 16 KB + B 32 KB
#define SMEM_GEMM (3*STG48)

__device__ __forceinline__ void gemm_issue_stage(
    uint32_t s, int tid, int m0, int n0, int kc,
    const __half* __restrict__ A, const __half* __restrict__ B)
{
    const int g = tid & 7;
#pragma unroll
    for (int i = 0; i < 4; i++) {
        int row = (tid + i * 256) >> 3;
        uint32_t o = row * 128 + g * 16; o ^= (o >> 3) & 0x70;
        CP16(s + o, A + (size_t)(m0 + row) * DM + kc + g * 8);
    }
#pragma unroll
    for (int i = 0; i < 8; i++) {
        int row = (tid + i * 256) >> 3;
        uint32_t o = row * 128 + g * 16; o ^= (o >> 3) & 0x70;
        CP16(s + 16384 + o, B + (size_t)(n0 + row) * DM + kc + g * 8);
    }
}

__global__ __launch_bounds__(256, 1) void gemm_mma_kernel(
    const __half* __restrict__ A, const __half* __restrict__ B,
    float* __restrict__ Cf, __half* __restrict__ Ch0,
    __half* __restrict__ Ch1, __half* __restrict__ Ch2,
    int do_relu, float scale)
{
    extern __shared__ char smem[];
    const uint32_t sb = smem_u32(smem);
    const int tid = threadIdx.x;
    const int lane = tid & 31;
    const int wid = tid >> 5;
    const int wm = wid & 1;
    const int wn = wid >> 1;
    const int m0 = blockIdx.y * 128;
    const int n0 = blockIdx.x * 256;

    float acc[4][8][4];
#pragma unroll
    for (int mt = 0; mt < 4; mt++)
#pragma unroll
        for (int nt = 0; nt < 8; nt++)
#pragma unroll
            for (int r = 0; r < 4; r++) acc[mt][nt][r] = 0.f;

    const int a_row = lane & 15;
    const int a_kb  = (lane >> 4) << 4;
    const int b_row = ((lane >> 4) << 3) + (lane & 7);
    const int b_kb  = ((lane >> 3) & 1) << 4;

    gemm_issue_stage(sb, tid, m0, n0, 0, A, B);
    CP_COMMIT();
    gemm_issue_stage(sb + STG48, tid, m0, n0, 64, A, B);
    CP_COMMIT();

    for (int c = 0; c < NCH; c++) {
        if (c + 1 < NCH) CP_WAIT1(); else CP_WAIT0();
        __syncthreads();

        const uint32_t sA = sb + (c % 3) * STG48;
        const uint32_t sB = sA + 16384;

#pragma unroll
        for (int kk = 0; kk < 4; kk++) {
            const int kbyte = kk * 32;
            uint32_t af[4][4], bfr[8][2];

#pragma unroll
            for (int mt = 0; mt < 4; mt++) {
                uint32_t o = (uint32_t)(wm*64 + mt*16 + a_row) * 128 + kbyte + a_kb;
                o ^= (o >> 3) & 0x70;
                LDSM4(af[mt], sA + o);
            }
#pragma unroll
            for (int p = 0; p < 4; p++) {
                uint32_t rr[4];
                uint32_t o = (uint32_t)(wn*64 + p*16 + b_row) * 128 + kbyte + b_kb;
                o ^= (o >> 3) & 0x70;
                LDSM4(rr, sB + o);
                bfr[p*2][0]   = rr[0]; bfr[p*2][1]   = rr[1];
                bfr[p*2+1][0] = rr[2]; bfr[p*2+1][1] = rr[3];
            }
#pragma unroll
            for (int mt = 0; mt < 4; mt++)
#pragma unroll
                for (int nt = 0; nt < 8; nt++)
                    MMA16816(acc[mt][nt], af[mt], bfr[nt]);
        }

        if (c + 2 < NCH) {
            gemm_issue_stage(sb + ((c + 2) % 3) * STG48, tid, m0, n0,
                             (c + 2) * 64, A, B);
            CP_COMMIT();
        }
    }

    const int which = n0 >> 10;
    __half* Ch = (which == 0) ? Ch0 : ((which == 1) ? Ch1 : Ch2);
    const int ncol = n0 & 1023;
    const float sc = (which == 0) ? scale : 1.f;

#pragma unroll
    for (int mt = 0; mt < 4; mt++) {
        int r0 = m0 + wm*64 + mt*16 + (lane >> 2);
#pragma unroll
        for (int nt = 0; nt < 8; nt++) {
            int cc = ncol + wn*64 + nt*8 + (lane & 3)*2;
            float v[4];
#pragma unroll
            for (int r = 0; r < 4; r++) {
                v[r] = acc[mt][nt][r] * sc;
                if (do_relu) v[r] = fmaxf(v[r], 0.f);
            }
            if (Cf) {
                *(float2*)(Cf + (size_t)r0 * DM + cc)       = make_float2(v[0], v[1]);
                *(float2*)(Cf + (size_t)(r0 + 8) * DM + cc) = make_float2(v[2], v[3]);
            }
            if (Ch) {
                *(uint32_t*)(Ch + (size_t)r0 * DM + cc)     = packh(v[0], v[1]);
                *(uint32_t*)(Ch + (size_t)(r0+8) * DM + cc) = packh(v[2], v[3]);
            }
        }
    }
}

// ===== prep: transpose+cvt 6 weights (z=0..5) + query cvt (z=6) ==========
struct PrepArgs {
    const float* w[6];
    const float4* q;
    uint2* qd;
};

__global__ __launch_bounds__(256) void prep_kernel(
    PrepArgs pa, __half* __restrict__ T)
{
    const int wz = blockIdx.z;
    if (wz < 6) {
        __shared__ float t[64][33];
        const float* W = pa.w[wz];
        __half* th = T + (size_t)wz * DM * DM;
        const int n0 = blockIdx.x * 32, k0 = blockIdx.y * 64;
        const int tx = threadIdx.x & 31, ty = threadIdx.x >> 5;
#pragma unroll
        for (int r = 0; r < 8; r++)
            t[ty + r*8][tx] = W[(size_t)(k0 + ty + r*8) * DM + n0 + tx];
        __syncthreads();
        const int tid = threadIdx.x;
#pragma unroll
        for (int w = 0; w < 4; w++) {
            int idx = tid + w * 256;
            int nl = idx >> 5;
            int u  = idx & 31;
            uint32_t pk = packh(t[2*u][nl], t[2*u+1][nl]);
            *(uint32_t*)(th + (size_t)(n0 + nl) * DM + k0 + 2*u) = pk;
        }
    } else {
        const int blk = blockIdx.y * 32 + blockIdx.x;
#pragma unroll
        for (int w = 0; w < 8; w++) {
            int i = (blk * 8 + w) * 256 + threadIdx.x;
            float4 v = pa.q[i];
            uint2 o;
            o.x = packh(v.x, v.y);
            o.y = packh(v.z, v.w);
            pa.qd[i] = o;
        }
    }
}

// ================ tensor-core flash attention, fp16 =======================
// 2 q-tiles per CTA (Br=256): kf/vf fragments shared across both tiles so
// LDSM-per-MMA halves. exp2 softmax, Q frags hoisted, 3-stage KV pipeline,
// single __syncthreads per iteration, vf double-buffered. 1 CTA/SM.
#define AT_Q 0              // 32 KB (256 rows)
#define AT_STG 32768
#define AT_STGSZ 16384      // K 8KB + V 8KB
#define SMEM_ATTN (32768 + 3*16384)   // 80 KB
#define NKT (SS/64)

__device__ __forceinline__ void attn_issue_kv(
    uint32_t s, int tid, size_t base, int kt,
    const __half* __restrict__ K, const __half* __restrict__ V)
{
#pragma unroll
    for (int i = 0; i < 2; i++) {
        int idx = tid + i * 256;
        int row = idx >> 3, c16 = idx & 7;
        uint32_t off = row * 128 + c16 * 16;
        off ^= (off >> 3) & 0x70;
        size_t g = base + (size_t)(kt * 64 + row) * DM + c16 * 8;
        CP16(s + off,        K + g);
        CP16(s + 8192 + off, V + g);
    }
}

__global__ __launch_bounds__(256, 1) void attn_mma_kernel(
    const __half* __restrict__ Q, const __half* __restrict__ K,
    const __half* __restrict__ V, __half* __restrict__ O)
{
    extern __shared__ char smem[];
    const uint32_t sb = smem_u32(smem);
    const int tid = threadIdx.x, lane = tid & 31, w = tid >> 5;
    const int q0 = blockIdx.x * 256;
    const int h = blockIdx.y, b = blockIdx.z;
    const size_t base = (size_t)b * SS * DM + h * DHD;

    // Q tile: 256 rows x 128B (group 0), then KV stages 0, 1
#pragma unroll
    for (int i = 0; i < 8; i++) {
        int idx = tid + i * 256;
        int row = idx >> 3, c16 = idx & 7;
        uint32_t off = row * 128 + c16 * 16;
        off ^= (off >> 3) & 0x70;
        CP16(sb + AT_Q + off, Q + base + (size_t)(q0 + row) * DM + c16 * 8);
    }
    CP_COMMIT();
    attn_issue_kv(sb + AT_STG + 0 * AT_STGSZ, tid, base, 0, K, V);
    CP_COMMIT();
    attn_issue_kv(sb + AT_STG + 1 * AT_STGSZ, tid, base, 1, K, V);
    CP_COMMIT();

    const int arow = w * 16 + (lane & 15);
    const int akb  = (lane >> 4) << 4;
    const int kp_row = ((lane >> 4) << 3) + (lane & 7);
    const int kp_kb  = ((lane >> 3) & 1) << 4;
    const int vp_row = lane & 15;
    const int vp_nb  = (lane >> 4) << 4;

    CP_WAIT2();
    __syncthreads();
    uint32_t aqr[2][4][4];
#pragma unroll
    for (int t = 0; t < 2; t++)
#pragma unroll
        for (int ks = 0; ks < 4; ks++) {
            uint32_t o = (uint32_t)(t * 128 + arow) * 128 + ks * 32 + akb;
            o ^= (o >> 3) & 0x70;
            LDSM4(aqr[t][ks], sb + AT_Q + o);
        }

    float acco[2][8][4];
#pragma unroll
    for (int t = 0; t < 2; t++)
#pragma unroll
        for (int nt = 0; nt < 8; nt++)
#pragma unroll
            for (int r = 0; r < 4; r++) acco[t][nt][r] = 0.f;
    float runm[2][2] = {{-1e30f, -1e30f}, {-1e30f, -1e30f}};
    float runs[2][2] = {{0.f, 0.f}, {0.f, 0.f}};

    uint32_t vf[2][4][4];

    for (int kt = 0; kt < NKT; kt++) {
        if (kt + 1 < NKT) CP_WAIT1(); else CP_WAIT0();
        __syncthreads();
        if (kt + 2 < NKT) {
            attn_issue_kv(sb + AT_STG + ((kt + 2) % 3) * AT_STGSZ, tid, base,
                          kt + 2, K, V);
            CP_COMMIT();
        }

        const uint32_t sK = sb + AT_STG + (kt % 3) * AT_STGSZ;
        const uint32_t sV = sK + 8192;

        auto ldv = [&](int bsel, int j) {
#pragma unroll
            for (int np = 0; np < 4; np++) {
                uint32_t vo = (uint32_t)(j * 16 + vp_row) * 128 + np * 32 + vp_nb;
                vo ^= (vo >> 3) & 0x70;
                LDSM4T(vf[bsel][np], sV + vo);
            }
        };

        // ---- QK^T: shared kf across both q-tiles ----
        float accs[2][8][4];
#pragma unroll
        for (int t = 0; t < 2; t++)
#pragma unroll
            for (int nt = 0; nt < 8; nt++)
#pragma unroll
                for (int r = 0; r < 4; r++) accs[t][nt][r] = 0.f;

#pragma unroll
        for (int ks = 0; ks < 4; ks++) {
            uint32_t kf[4][4];
#pragma unroll
            for (int p = 0; p < 4; p++) {
                uint32_t bo = (uint32_t)(p * 16 + kp_row) * 128 + ks * 32 + kp_kb;
                bo ^= (bo >> 3) & 0x70;
                LDSM4(kf[p], sK + bo);
            }
#pragma unroll
            for (int p = 0; p < 4; p++) {
                MMA16816(accs[0][p*2],   aqr[0][ks], (kf[p]));
                MMA16816(accs[0][p*2+1], aqr[0][ks], (kf[p] + 2));
                MMA16816(accs[1][p*2],   aqr[1][ks], (kf[p]));
                MMA16816(accs[1][p*2+1], aqr[1][ks], (kf[p] + 2));
            }
        }

        ldv(0, 0);   // prefetch V j=0, overlaps softmax

        // ---- online softmax (base 2), both tiles ----
#pragma unroll
        for (int t = 0; t < 2; t++) {
            float mx0 = -1e30f, mx1 = -1e30f;
#pragma unroll
            for (int nt = 0; nt < 8; nt++) {
                mx0 = fmaxf(mx0, fmaxf(accs[t][nt][0], accs[t][nt][1]));
                mx1 = fmaxf(mx1, fmaxf(accs[t][nt][2], accs[t][nt][3]));
            }
            mx0 = fmaxf(mx0, __shfl_xor_sync(0xffffffffu, mx0, 1));
            mx0 = fmaxf(mx0, __shfl_xor_sync(0xffffffffu, mx0, 2));
            mx1 = fmaxf(mx1, __shfl_xor_sync(0xffffffffu, mx1, 1));
            mx1 = fmaxf(mx1, __shfl_xor_sync(0xffffffffu, mx1, 2));

            if (mx0 > runm[t][0] || mx1 > runm[t][1]) {
                float nm0 = fmaxf(runm[t][0], mx0), nm1 = fmaxf(runm[t][1], mx1);
                float c0 = exp2f(runm[t][0] - nm0), c1 = exp2f(runm[t][1] - nm1);
                runm[t][0] = nm0; runm[t][1] = nm1;
                runs[t][0] *= c0; runs[t][1] *= c1;
#pragma unroll
                for (int nt = 0; nt < 8; nt++) {
                    acco[t][nt][0] *= c0; acco[t][nt][1] *= c0;
                    acco[t][nt][2] *= c1; acco[t][nt][3] *= c1;
                }
            }

            float s0 = 0.f, s1 = 0.f;
#pragma unroll
            for (int nt = 0; nt < 8; nt++) {
                accs[t][nt][0] = exp2f(accs[t][nt][0] - runm[t][0]); s0 += accs[t][nt][0];
                accs[t][nt][1] = exp2f(accs[t][nt][1] - runm[t][0]); s0 += accs[t][nt][1];
                accs[t][nt][2] = exp2f(accs[t][nt][2] - runm[t][1]); s1 += accs[t][nt][2];
                accs[t][nt][3] = exp2f(accs[t][nt][3] - runm[t][1]); s1 += accs[t][nt][3];
            }
            s0 += __shfl_xor_sync(0xffffffffu, s0, 1);
            s0 += __shfl_xor_sync(0xffffffffu, s0, 2);
            s1 += __shfl_xor_sync(0xffffffffu, s1, 1);
            s1 += __shfl_xor_sync(0xffffffffu, s1, 2);
            runs[t][0] += s0;
            runs[t][1] += s1;
        }

        // ---- P @ V: shared vf across both tiles, double-buffered ----
#pragma unroll
        for (int j = 0; j < 4; j++) {
            if (j < 3) ldv((j + 1) & 1, j + 1);
            const int cur = j & 1;
            uint32_t ap0[4], ap1[4];
            {
                float* pa = accs[0][2*j];
                float* pb = accs[0][2*j + 1];
                ap0[0] = packh(pa[0], pa[1]);
                ap0[1] = packh(pa[2], pa[3]);
                ap0[2] = packh(pb[0], pb[1]);
                ap0[3] = packh(pb[2], pb[3]);
                pa = accs[1][2*j];
                pb = accs[1][2*j + 1];
                ap1[0] = packh(pa[0], pa[1]);
                ap1[1] = packh(pa[2], pa[3]);
                ap1[2] = packh(pb[0], pb[1]);
                ap1[3] = packh(pb[2], pb[3]);
            }
#pragma unroll
            for (int np = 0; np < 4; np++) {
                MMA16816(acco[0][np*2],   ap0, (vf[cur][np]));
                MMA16816(acco[0][np*2+1], ap0, (vf[cur][np] + 2));
                MMA16816(acco[1][np*2],   ap1, (vf[cur][np]));
                MMA16816(acco[1][np*2+1], ap1, (vf[cur][np] + 2));
            }
        }
    }

    // ---- epilogue: both tiles ----
#pragma unroll
    for (int t = 0; t < 2; t++) {
        const float i0 = 1.f / runs[t][0], i1 = 1.f / runs[t][1];
        const size_t r0 = (size_t)(b * SS + q0 + t * 128 + w * 16 + (lane >> 2));
#pragma unroll
        for (int nt = 0; nt < 8; nt++) {
            int cc = h * DHD + nt * 8 + (lane & 3) * 2;
            *(uint32_t*)(O + r0 * DM + cc) =
                packh(acco[t][nt][0]*i0, acco[t][nt][1]*i0);
            *(uint32_t*)(O + (r0+8) * DM + cc) =
                packh(acco[t][nt][2]*i1, acco[t][nt][3]*i1);
        }
    }
}

// ======================= residual-add + LayerNorm =========================
__device__ __forceinline__ float block_sum256(float v, float* red) {
#pragma unroll
    for (int o = 16; o; o >>= 1) v += __shfl_xor_sync(0xffffffffu, v, o);
    int lane = threadIdx.x & 31, wid = threadIdx.x >> 5;
    if (lane == 0) red[wid] = v;
    __syncthreads();
    if (threadIdx.x < 32) {
        float t = (threadIdx.x < 8) ? red[threadIdx.x] : 0.f;
#pragma unroll
        for (int o = 4; o; o >>= 1) t += __shfl_xor_sync(0xffffffffu, t, o);
        if (threadIdx.x == 0) red[0] = t;
    }
    __syncthreads();
    float r = red[0];
    __syncthreads();
    return r;
}

__global__ __launch_bounds__(256) void ln_kernel(
    const float* __restrict__ x, const float* __restrict__ res,
    const float* __restrict__ gamma, const float* __restrict__ beta,
    float* __restrict__ out, __half* __restrict__ oh)
{
    __shared__ float red[8];
    const int row = blockIdx.x;
    const int tid = threadIdx.x;

    float4 v = ((const float4*)(x + (size_t)row * DM))[tid];
    float4 r = ((const float4*)(res + (size_t)row * DM))[tid];
    v.x += r.x; v.y += r.y; v.z += r.z; v.w += r.w;

    float s = v.x + v.y + v.z + v.w;
    float tot = block_sum256(s, red);
    float mean = tot * (1.f / DM);

    float dx = v.x - mean, dy = v.y - mean, dz = v.z - mean, dw = v.w - mean;
    float sq = dx*dx + dy*dy + dz*dz + dw*dw;
    float totsq = block_sum256(sq, red);
    float rstd = rsqrtf(totsq * (1.f / DM) + LN_EPS);

    float4 g = ((const float4*)gamma)[tid];
    float4 bb = ((const float4*)beta)[tid];
    float4 o;
    o.x = dx * rstd * g.x + bb.x;
    o.y = dy * rstd * g.y + bb.y;
    o.z = dz * rstd * g.z + bb.z;
    o.w = dw * rstd * g.w + bb.w;
    if (out) ((float4*)(out + (size_t)row * DM))[tid] = o;
    if (oh) {
        uint32_t* hp = (uint32_t*)(oh + (size_t)row * DM) + tid*2;
        hp[0] = packh(o.x, o.y);
        hp[1] = packh(o.z, o.w);
    }
}

// ================================ driver ==================================
extern "C" void kernel_launch(void* const* d_in, const int* in_sizes, int n_in,
                              void* d_out, int out_size)
{
    const float* query = (const float*)d_in[0];
    const float* gamma = (const float*)d_in[7];
    const float* beta  = (const float*)d_in[8];

    float *b0, *b1;
    __half *ah, *bh, *qh, *kh, *vh, *wt;
    cudaGetSymbolAddress((void**)&b0, g_buf0);
    cudaGetSymbolAddress((void**)&b1, g_buf1);
    cudaGetSymbolAddress((void**)&ah, g_a);
    cudaGetSymbolAddress((void**)&bh, g_b);
    cudaGetSymbolAddress((void**)&qh, g_q);
    cudaGetSymbolAddress((void**)&kh, g_k);
    cudaGetSymbolAddress((void**)&vh, g_v);
    cudaGetSymbolAddress((void**)&wt, g_wt);

    cudaFuncSetAttribute(gemm_mma_kernel,
                         cudaFuncAttributeMaxDynamicSharedMemorySize, SMEM_GEMM);
    cudaFuncSetAttribute(attn_mma_kernel,
                         cudaFuncAttributeMaxDynamicSharedMemorySize, SMEM_ATTN);

    const dim3 ggrid(DM / 256, MROWS / 128);          // (4, 32)
    const dim3 ggrid_qkv(3 * DM / 256, MROWS / 128);  // (12, 32)
    const float QSCALE = 0.125f * 1.44269504088896f;  // fold log2(e) for exp2

    // merged prep: 6 weight transpose+cvt slices + query cvt slice
    PrepArgs pa;
    for (int i = 0; i < 6; i++) pa.w[i] = (const float*)d_in[1 + i];
    pa.q  = (const float4*)query;
    pa.qd = (uint2*)ah;
    prep_kernel<<<dim3(DM/32, DM/64, 7), 256>>>(pa, wt);

    // merged QKV projection (N = 3072; Q pre-scaled into exp2 domain)
    gemm_mma_kernel<<<ggrid_qkv, 256, SMEM_GEMM>>>(
        ah, wt, nullptr, qh, kh, vh, 0, QSCALE);

    // attention -> ctx fp16 in ah (2 q-tiles per CTA)
    attn_mma_kernel<<<dim3(SS/256, HH, BB), 256, SMEM_ATTN>>>(qh, kh, vh, ah);

    // ctx @ W1 -> fp32 b0 ; LN(b0 + query) -> fp32 b1 + fp16 ah
    gemm_mma_kernel<<<ggrid, 256, SMEM_GEMM>>>(
        ah, wt + 3*(size_t)DM*DM, b0, nullptr, nullptr, nullptr, 0, 1.f);
    ln_kernel<<<MROWS, 256>>>(b0, query, gamma, beta, b1, ah);

    // relu(residual @ W2) -> fp16 bh ; bh @ W3 -> fp32 b0 ; LN -> out
    gemm_mma_kernel<<<ggrid, 256, SMEM_GEMM>>>(
        ah, wt + 4*(size_t)DM*DM, nullptr, bh, bh, bh, 1, 1.f);
    gemm_mma_kernel<<<ggrid, 256, SMEM_GEMM>>>(
        bh, wt + 5*(size_t)DM*DM, b0, nullptr, nullptr, nullptr, 0, 1.f);
    ln_kernel<<<MROWS, 256>>>(b0, b1, gamma, beta, (float*)d_out, nullptr);
}